// round 2
// baseline (speedup 1.0000x reference)
#include <cuda_runtime.h>
#include <cuda_bf16.h>

// HierarchicalDistanceLoss: B=1048576 rows, C=40 classes.
// out[0] = mean(ce * df) ; out[1..B] = df, when out_size > B.
//
// Single fused kernel, 4096 blocks x 256 threads, 256 rows/block:
//   - Stage 256x40 f32 logits tile into smem via coalesced float4 loads,
//     pitch 44 floats (176B, 16B-aligned, LDS.128 bank-conflict-free).
//   - Each thread loads its row once (10x float4 LDS) into registers;
//     max/argmax + sum(exp) from registers.
//   - ce = m + log(S) - x[lbl]; df = dis[lbl*40+am] + 0.5.
//   - Block partial -> g_hdl_partials; last block (atomic ticket) reduces
//     all 4096 partials in fixed order -> out[0]. Counter self-resets,
//     so every graph replay is bitwise identical.

#define HDL_B 1048576
#define HDL_C 40
#define HDL_BLOCKS 4096
#define HDL_TPB 256
#define HDL_PITCH 44  // floats; 176B rows, 16B aligned, LDS.128 conflict-free

__device__ float g_hdl_partials[HDL_BLOCKS];
__device__ unsigned int g_hdl_ticket;  // zero-init; self-resetting

__global__ __launch_bounds__(HDL_TPB) void hdl_fused_kernel(
    const float* __restrict__ logits,
    const int* __restrict__ labels,
    const float* __restrict__ dis,
    float* __restrict__ out,
    int df_offset, int store_df, int write_loss)
{
    __shared__ float s[HDL_TPB * HDL_PITCH];   // 256*44*4 = 45056 B
    __shared__ float wsum[HDL_TPB / 32];
    __shared__ int s_is_last;

    const int tid = threadIdx.x;
    const long long row_base = (long long)blockIdx.x * HDL_TPB;

    // ---- coalesced staged load: 256 rows * 10 float4 each ----
    const float4* g4 = reinterpret_cast<const float4*>(logits) + row_base * (HDL_C / 4);
    #pragma unroll
    for (int k = 0; k < 10; k++) {
        int idx = k * HDL_TPB + tid;          // contiguous across warp
        int row = idx / 10;
        int q   = idx % 10;
        float4 v = __ldcs(&g4[idx]);          // streaming: no reuse
        *reinterpret_cast<float4*>(&s[row * HDL_PITCH + q * 4]) = v;
    }
    __syncthreads();

    // ---- row -> registers (10x LDS.128, conflict-free) ----
    float x[HDL_C];
    {
        const float4* xv = reinterpret_cast<const float4*>(&s[tid * HDL_PITCH]);
        #pragma unroll
        for (int q = 0; q < 10; q++) {
            float4 v = xv[q];
            x[q * 4 + 0] = v.x; x[q * 4 + 1] = v.y;
            x[q * 4 + 2] = v.z; x[q * 4 + 3] = v.w;
        }
    }

    // ---- max / argmax (strict '>' keeps FIRST max) ----
    float m = x[0];
    int am = 0;
    #pragma unroll
    for (int c = 1; c < HDL_C; c++) {
        if (x[c] > m) { m = x[c]; am = c; }
    }
    // ---- sum(exp(x - m)) ----
    float ssum = 0.0f;
    #pragma unroll
    for (int c = 0; c < HDL_C; c++)
        ssum += __expf(x[c] - m);

    const long long grow = row_base + tid;
    const int lbl = labels[grow];
    const float ce = m + __logf(ssum) - x[lbl];
    const float df = __ldg(&dis[lbl * HDL_C + am]) + 0.5f;

    if (store_df) __stcs(&out[df_offset + grow], df);

    // ---- deterministic block reduction of ce*df ----
    float val = ce * df;
    #pragma unroll
    for (int o = 16; o > 0; o >>= 1)
        val += __shfl_down_sync(0xFFFFFFFFu, val, o);
    if ((tid & 31) == 0) wsum[tid >> 5] = val;
    __syncthreads();
    if (tid == 0) {
        float acc = 0.0f;
        #pragma unroll
        for (int w = 0; w < HDL_TPB / 32; w++) acc += wsum[w];
        g_hdl_partials[blockIdx.x] = acc;
        __threadfence();
        unsigned int t = atomicAdd(&g_hdl_ticket, 1u);
        s_is_last = (t == (unsigned int)(HDL_BLOCKS - 1)) ? 1 : 0;
    }
    __syncthreads();

    // ---- last block: reduce 4096 partials in fixed order ----
    if (s_is_last) {
        float acc = 0.0f;
        #pragma unroll
        for (int i = 0; i < HDL_BLOCKS / HDL_TPB; i++) {
            // volatile-ish read: bypass L1 so producers' writes are seen
            float p;
            asm volatile("ld.global.cg.f32 %0, [%1];"
                         : "=f"(p) : "l"(&g_hdl_partials[tid + i * HDL_TPB]));
            acc += p;
        }
        #pragma unroll
        for (int o = 16; o > 0; o >>= 1)
            acc += __shfl_down_sync(0xFFFFFFFFu, acc, o);
        if ((tid & 31) == 0) wsum[tid >> 5] = acc;
        __syncthreads();
        if (tid == 0) {
            float tot = 0.0f;
            #pragma unroll
            for (int w = 0; w < HDL_TPB / 32; w++) tot += wsum[w];
            if (write_loss) out[0] = tot * (1.0f / (float)HDL_B);
            g_hdl_ticket = 0;   // reset for next graph replay
        }
    }
}

extern "C" void kernel_launch(void* const* d_in, const int* in_sizes, int n_in,
                              void* d_out, int out_size)
{
    const float* logits = (const float*)d_in[0];
    const int*   labels = (const int*)d_in[1];
    const float* dis    = (const float*)d_in[2];
    float* out = (float*)d_out;

    const int has_loss = (out_size != HDL_B) ? 1 : 0;
    const int df_off   = (out_size > HDL_B) ? 1 : 0;
    const int store_df = (out_size >= HDL_B) ? 1 : 0;

    hdl_fused_kernel<<<HDL_BLOCKS, HDL_TPB>>>(logits, labels, dis, out,
                                              df_off, store_df, has_loss);
}

// round 7
// speedup vs baseline: 1.5923x; 1.5923x over previous
#include <cuda_runtime.h>
#include <cuda_bf16.h>

// HierarchicalDistanceLoss: B=1048576 rows, C=40 classes.
// out[0] = mean(ce * df) ; out[1..B] = df, when out_size > B.
//
// Single fused kernel, 4096 blocks x 256 threads, 256 rows/block:
//   - labels LDG issued before the staging loop (latency overlapped).
//   - Stage 256x40 f32 logits tile into smem via coalesced float4 loads,
//     pitch 44 floats (176B, 16B-aligned, LDS.128 bank-conflict-free).
//   - Pass 1: 10x LDS.128 -> max/argmax (strict '>', first max).
//   - Pass 2: 10x LDS.128 -> sum(exp(x-m)). No register array -> no spill;
//     x[lbl] is one scalar LDS.
//   - ce = m + log(S) - x[lbl]; df = dis[lbl*40+am] + 0.5.
//   - Deterministic fused reduction: block partial -> g_hdl_partials; last
//     block (atomic ticket, self-resetting) sums 4096 partials in fixed
//     order -> out[0]. Bitwise identical on every graph replay.

#define HDL_B 1048576
#define HDL_C 40
#define HDL_BLOCKS 4096
#define HDL_TPB 256
#define HDL_PITCH 44  // floats; 176B rows, 16B aligned, LDS.128 conflict-free

__device__ float g_hdl_partials[HDL_BLOCKS];
__device__ unsigned int g_hdl_ticket;  // zero-init; self-resetting

__global__ __launch_bounds__(HDL_TPB) void hdl_fused_kernel(
    const float* __restrict__ logits,
    const int* __restrict__ labels,
    const float* __restrict__ dis,
    float* __restrict__ out,
    int df_offset, int store_df, int write_loss)
{
    __shared__ float s[HDL_TPB * HDL_PITCH];   // 256*44*4 = 45056 B
    __shared__ float wsum[HDL_TPB / 32];
    __shared__ int s_is_last;

    const int tid = threadIdx.x;
    const long long row_base = (long long)blockIdx.x * HDL_TPB;
    const long long grow = row_base + tid;

    // Issue label load early; latency hides under the staging loop.
    const int lbl = __ldg(&labels[grow]);

    // ---- coalesced staged load: 256 rows * 10 float4 each ----
    const float4* g4 = reinterpret_cast<const float4*>(logits) + row_base * (HDL_C / 4);
    #pragma unroll
    for (int k = 0; k < 10; k++) {
        int idx = k * HDL_TPB + tid;          // contiguous across warp
        int row = idx / 10;
        int q   = idx % 10;
        float4 v = __ldcs(&g4[idx]);          // streaming: no reuse
        *reinterpret_cast<float4*>(&s[row * HDL_PITCH + q * 4]) = v;
    }
    __syncthreads();

    const float4* xv = reinterpret_cast<const float4*>(&s[tid * HDL_PITCH]);

    // ---- pass 1: max / argmax (strict '>' keeps FIRST max) ----
    float m = -3.402823466e+38f;
    int am = 0;
    #pragma unroll
    for (int q = 0; q < 10; q++) {
        float4 v = xv[q];
        if (v.x > m) { m = v.x; am = q * 4 + 0; }
        if (v.y > m) { m = v.y; am = q * 4 + 1; }
        if (v.z > m) { m = v.z; am = q * 4 + 2; }
        if (v.w > m) { m = v.w; am = q * 4 + 3; }
    }

    // ---- pass 2: sum(exp(x - m)) ----
    float ssum = 0.0f;
    #pragma unroll
    for (int q = 0; q < 10; q++) {
        float4 v = xv[q];
        ssum += __expf(v.x - m);
        ssum += __expf(v.y - m);
        ssum += __expf(v.z - m);
        ssum += __expf(v.w - m);
    }

    const float xl = s[tid * HDL_PITCH + lbl];        // single scalar LDS
    const float ce = m + __logf(ssum) - xl;
    const float df = __ldg(&dis[lbl * HDL_C + am]) + 0.5f;

    if (store_df) __stcs(&out[df_offset + grow], df);

    // ---- deterministic block reduction of ce*df ----
    float val = ce * df;
    #pragma unroll
    for (int o = 16; o > 0; o >>= 1)
        val += __shfl_down_sync(0xFFFFFFFFu, val, o);
    if ((tid & 31) == 0) wsum[tid >> 5] = val;
    __syncthreads();
    if (tid == 0) {
        float acc = 0.0f;
        #pragma unroll
        for (int w = 0; w < HDL_TPB / 32; w++) acc += wsum[w];
        g_hdl_partials[blockIdx.x] = acc;
        __threadfence();
        unsigned int t = atomicAdd(&g_hdl_ticket, 1u);
        s_is_last = (t == (unsigned int)(HDL_BLOCKS - 1)) ? 1 : 0;
    }
    __syncthreads();

    // ---- last block: reduce 4096 partials in fixed order ----
    if (s_is_last) {
        float acc = 0.0f;
        #pragma unroll
        for (int i = 0; i < HDL_BLOCKS / HDL_TPB; i++) {
            float p;
            asm volatile("ld.global.cg.f32 %0, [%1];"
                         : "=f"(p) : "l"(&g_hdl_partials[tid + i * HDL_TPB]));
            acc += p;
        }
        #pragma unroll
        for (int o = 16; o > 0; o >>= 1)
            acc += __shfl_down_sync(0xFFFFFFFFu, acc, o);
        if ((tid & 31) == 0) wsum[tid >> 5] = acc;
        __syncthreads();
        if (tid == 0) {
            float tot = 0.0f;
            #pragma unroll
            for (int w = 0; w < HDL_TPB / 32; w++) tot += wsum[w];
            if (write_loss) out[0] = tot * (1.0f / (float)HDL_B);
            g_hdl_ticket = 0;   // reset for next graph replay
        }
    }
}

extern "C" void kernel_launch(void* const* d_in, const int* in_sizes, int n_in,
                              void* d_out, int out_size)
{
    const float* logits = (const float*)d_in[0];
    const int*   labels = (const int*)d_in[1];
    const float* dis    = (const float*)d_in[2];
    float* out = (float*)d_out;

    const int has_loss = (out_size != HDL_B) ? 1 : 0;
    const int df_off   = (out_size > HDL_B) ? 1 : 0;
    const int store_df = (out_size >= HDL_B) ? 1 : 0;

    hdl_fused_kernel<<<HDL_BLOCKS, HDL_TPB>>>(logits, labels, dis, out,
                                              df_off, store_df, has_loss);
}